// round 1
// baseline (speedup 1.0000x reference)
#include <cuda_runtime.h>
#include <math.h>
#include <stdint.h>

// ---------------- problem constants ----------------
#define Bq   64
#define Dd   768
#define Nn   262144
#define Vv   50257
#define Kk   8
#define TEMP 10.0f
#define LAM  0.25f
#define EPSV 1e-10f

#define CHUNK  256                 // keys per block in score kernel
#define NCHUNK (Nn / CHUNK)        // 1024
#define DTILE  32
#define NDT    (Dd / DTILE)        // 24

typedef unsigned long long u64;

// ---------------- scratch (static device globals; no allocation) ----------------
__device__ float g_cs[Bq * NCHUNK * Kk];   // candidate scores  (2 MB)
__device__ int   g_ci[Bq * NCHUNK * Kk];   // candidate indices (2 MB)
__device__ float g_w[Bq * Kk];             // final neighbor weights
__device__ int   g_tok[Bq * Kk];           // final neighbor tokens
__device__ float g_sumw[Bq];
__device__ float g_rowmax[Bq];
__device__ float g_rowsum[Bq];

// ---------------- packed f32x2 helpers (Blackwell) ----------------
__device__ __forceinline__ u64 pk2(float x, float y) {
    u64 r; asm("mov.b64 %0, {%1, %2};" : "=l"(r) : "f"(x), "f"(y)); return r;
}
__device__ __forceinline__ void upk2(u64 v, float& x, float& y) {
    asm("mov.b64 {%0, %1}, %2;" : "=f"(x), "=f"(y) : "l"(v));
}
__device__ __forceinline__ u64 ffma2(u64 a, u64 b, u64 c) {
    u64 d; asm("fma.rn.f32x2 %0, %1, %2, %3;" : "=l"(d) : "l"(a), "l"(b), "l"(c)); return d;
}

// =====================================================================
// Kernel 1: score = q.k - 0.5*||k||^2 for a 256-key chunk x all 64 queries,
// then in-register warp top-8 per query -> per-chunk candidates.
// =====================================================================
__global__ __launch_bounds__(256, 2)
void k_scores(const float* __restrict__ qh, const float* __restrict__ keys) {
    __shared__ float q_sm[DTILE][64];
    __shared__ float k_sm[DTILE][260];   // pad 260 keeps 16B alignment
    __shared__ float k2_sm[CHUNK];

    const int tid = threadIdx.x;
    const int tx  = tid & 31;    // key group: keys [tx*8, tx*8+8)
    const int ty  = tid >> 5;    // query group: queries [ty*8, ty*8+8)
    const int kBase = blockIdx.x * CHUNK;

    u64 acc[8][4];
    #pragma unroll
    for (int q = 0; q < 8; ++q)
        #pragma unroll
        for (int p = 0; p < 4; ++p) acc[q][p] = 0ull;
    u64 k2a[4] = {0ull, 0ull, 0ull, 0ull};

    for (int t = 0; t < NDT; ++t) {
        const int dBase = t * DTILE;
        // load Q tile: 64 rows x 8 float4
        {
            int i = tid;
            #pragma unroll
            for (int it = 0; it < 2; ++it) {
                int qrow = i >> 3, ds = i & 7;
                float4 v = *reinterpret_cast<const float4*>(&qh[qrow * Dd + dBase + ds * 4]);
                q_sm[ds * 4 + 0][qrow] = v.x; q_sm[ds * 4 + 1][qrow] = v.y;
                q_sm[ds * 4 + 2][qrow] = v.z; q_sm[ds * 4 + 3][qrow] = v.w;
                i += 256;
            }
        }
        // load K tile: 256 rows x 8 float4
        {
            int i = tid;
            #pragma unroll
            for (int it = 0; it < 8; ++it) {
                int kk = i >> 3, ds = i & 7;
                float4 v = *reinterpret_cast<const float4*>(&keys[(size_t)(kBase + kk) * Dd + dBase + ds * 4]);
                k_sm[ds * 4 + 0][kk] = v.x; k_sm[ds * 4 + 1][kk] = v.y;
                k_sm[ds * 4 + 2][kk] = v.z; k_sm[ds * 4 + 3][kk] = v.w;
                i += 256;
            }
        }
        __syncthreads();

        #pragma unroll 8
        for (int d = 0; d < DTILE; ++d) {
            float4 ka = *reinterpret_cast<const float4*>(&k_sm[d][tx * 8]);
            float4 kb = *reinterpret_cast<const float4*>(&k_sm[d][tx * 8 + 4]);
            u64 kp0 = pk2(ka.x, ka.y), kp1 = pk2(ka.z, ka.w);
            u64 kp2 = pk2(kb.x, kb.y), kp3 = pk2(kb.z, kb.w);
            float4 qa = *reinterpret_cast<const float4*>(&q_sm[d][ty * 8]);
            float4 qb = *reinterpret_cast<const float4*>(&q_sm[d][ty * 8 + 4]);
            float qv[8] = {qa.x, qa.y, qa.z, qa.w, qb.x, qb.y, qb.z, qb.w};
            #pragma unroll
            for (int q = 0; q < 8; ++q) {
                u64 qq = pk2(qv[q], qv[q]);
                acc[q][0] = ffma2(qq, kp0, acc[q][0]);
                acc[q][1] = ffma2(qq, kp1, acc[q][1]);
                acc[q][2] = ffma2(qq, kp2, acc[q][2]);
                acc[q][3] = ffma2(qq, kp3, acc[q][3]);
            }
            if (ty == 0) {   // warp-uniform: one warp accumulates ||k||^2
                k2a[0] = ffma2(kp0, kp0, k2a[0]);
                k2a[1] = ffma2(kp1, kp1, k2a[1]);
                k2a[2] = ffma2(kp2, kp2, k2a[2]);
                k2a[3] = ffma2(kp3, kp3, k2a[3]);
            }
        }
        __syncthreads();
    }

    if (ty == 0) {
        #pragma unroll
        for (int p = 0; p < 4; ++p) {
            float lo, hi; upk2(k2a[p], lo, hi);
            k2_sm[tx * 8 + 2 * p]     = 0.5f * lo;
            k2_sm[tx * 8 + 2 * p + 1] = 0.5f * hi;
        }
    }
    __syncthreads();

    // ------ per-query warp top-8 over this chunk's 256 keys ------
    for (int q = 0; q < 8; ++q) {
        float sc[8];
        #pragma unroll
        for (int p = 0; p < 4; ++p) {
            float lo, hi; upk2(acc[q][p], lo, hi);
            sc[2 * p]     = lo - k2_sm[tx * 8 + 2 * p];
            sc[2 * p + 1] = hi - k2_sm[tx * 8 + 2 * p + 1];
        }
        unsigned msk = 0;
        const int b = ty * 8 + q;
        for (int r = 0; r < Kk; ++r) {
            float best = -3.4e38f; int bi = 0;
            #pragma unroll
            for (int i = 0; i < 8; ++i)
                if (!((msk >> i) & 1u) && sc[i] > best) { best = sc[i]; bi = i; }
            int cand = (tx << 3) | bi;
            #pragma unroll
            for (int off = 16; off > 0; off >>= 1) {
                float ov = __shfl_down_sync(0xffffffffu, best, off);
                int   oc = __shfl_down_sync(0xffffffffu, cand, off);
                if (ov > best) { best = ov; cand = oc; }
            }
            best = __shfl_sync(0xffffffffu, best, 0);
            cand = __shfl_sync(0xffffffffu, cand, 0);
            if ((cand >> 3) == tx) msk |= 1u << (cand & 7);
            if (tx == 0) {
                size_t o = ((size_t)b * NCHUNK + blockIdx.x) * Kk + r;
                g_cs[o] = best;
                g_ci[o] = kBase + cand;
            }
        }
    }
}

// =====================================================================
// Kernel 2: per-query reduce 8192 candidates -> global top-8, compute
// softmax weights, gather tokens (auto-detect int64 vs int32 values).
// =====================================================================
__global__ __launch_bounds__(512)
void k_topk(const void* __restrict__ values_raw) {
    __shared__ float sval[512 * Kk];
    __shared__ int   sidx[512 * Kk];
    __shared__ float rv[512];
    __shared__ int   rp[512];
    __shared__ float topv[Kk];
    __shared__ int   topi[Kk];
    __shared__ int   is64;

    const int b = blockIdx.x;
    const int tid = threadIdx.x;
    const int M = NCHUNK * Kk;     // 8192

    // dtype detection: int64 tokens are < 2^31 -> high words all zero
    if (tid == 0) is64 = 1;
    __syncthreads();
    {
        const int2* vv = (const int2*)values_raw;
        int bad = 0;
        #pragma unroll
        for (int s = 0; s < 8; ++s) bad |= vv[tid + s * 512].y;
        if (bad != 0) is64 = 0;
    }

    // local top-8 by sorted insertion
    float lv[Kk]; int li[Kk];
    #pragma unroll
    for (int j = 0; j < Kk; ++j) { lv[j] = -3.4e38f; li[j] = 0; }
    const size_t base = (size_t)b * M;
    for (int s = 0; s < 16; ++s) {
        int j = tid + s * 512;
        float v = g_cs[base + j];
        int  ix = g_ci[base + j];
        if (v > lv[Kk - 1]) {
            lv[Kk - 1] = v; li[Kk - 1] = ix;
            #pragma unroll
            for (int t = Kk - 1; t >= 1; --t)
                if (lv[t] > lv[t - 1]) {
                    float tv = lv[t]; lv[t] = lv[t - 1]; lv[t - 1] = tv;
                    int   ti = li[t]; li[t] = li[t - 1]; li[t - 1] = ti;
                }
        }
    }
    #pragma unroll
    for (int j = 0; j < Kk; ++j) { sval[tid * Kk + j] = lv[j]; sidx[tid * Kk + j] = li[j]; }
    __syncthreads();

    // 8 rounds of block argmax over 4096 survivors
    for (int r = 0; r < Kk; ++r) {
        float best = -3.4e38f; int bp = 0;
        #pragma unroll
        for (int s = 0; s < Kk; ++s) {
            int p = tid + s * 512;
            if (sval[p] > best) { best = sval[p]; bp = p; }
        }
        rv[tid] = best; rp[tid] = bp;
        __syncthreads();
        for (int st = 256; st > 0; st >>= 1) {
            if (tid < st && rv[tid + st] > rv[tid]) { rv[tid] = rv[tid + st]; rp[tid] = rp[tid + st]; }
            __syncthreads();
        }
        if (tid == 0) {
            topv[r] = rv[0];
            topi[r] = sidx[rp[0]];
            sval[rp[0]] = -3.4e38f;
        }
        __syncthreads();
    }

    if (tid == 0) {
        float m = topv[0];
        float e[Kk], se = 0.f;
        #pragma unroll
        for (int r = 0; r < Kk; ++r) { e[r] = expf(2.f * (topv[r] - m) / TEMP); se += e[r]; }
        float sw = 0.f;
        #pragma unroll
        for (int r = 0; r < Kk; ++r) {
            float w = e[r] / se;
            g_w[b * Kk + r] = w; sw += w;
            int tok;
            if (is64) tok = (int)((const long long*)values_raw)[topi[r]];
            else      tok = ((const int*)values_raw)[topi[r]];
            g_tok[b * Kk + r] = tok;
        }
        g_sumw[b] = sw;
    }
}

// =====================================================================
// Kernel 3a: per-row max & sum(exp) of base_logits
// =====================================================================
__global__ __launch_bounds__(256)
void k_rowstats(const float* __restrict__ bl) {
    __shared__ float red[256];
    __shared__ float s_rm;
    const int b = blockIdx.x, tid = threadIdx.x;
    const float* row = bl + (size_t)b * Vv;

    float m = -3.4e38f;
    for (int v = tid; v < Vv; v += 256) m = fmaxf(m, row[v]);
    red[tid] = m; __syncthreads();
    for (int st = 128; st > 0; st >>= 1) {
        if (tid < st) red[tid] = fmaxf(red[tid], red[tid + st]);
        __syncthreads();
    }
    if (tid == 0) { s_rm = red[0]; g_rowmax[b] = red[0]; }
    __syncthreads();
    float rm = s_rm;

    float s = 0.f;
    for (int v = tid; v < Vv; v += 256) s += expf(row[v] - rm);
    red[tid] = s; __syncthreads();
    for (int st = 128; st > 0; st >>= 1) {
        if (tid < st) red[tid] += red[tid + st];
        __syncthreads();
    }
    if (tid == 0) g_rowsum[b] = red[0];
}

// =====================================================================
// Kernel 3b: final elementwise mix; writes (interpolated, base, knn)
// =====================================================================
__global__ __launch_bounds__(256)
void k_final(const float* __restrict__ bl, float* __restrict__ out, long long out_size) {
    __shared__ float ws[Kk]; __shared__ int ts[Kk];
    __shared__ float s_rm, s_rs, s_sw;
    const int b = blockIdx.y, tid = threadIdx.x;
    if (tid < Kk) { ws[tid] = g_w[b * Kk + tid]; ts[tid] = g_tok[b * Kk + tid]; }
    if (tid == 8)  s_rm = g_rowmax[b];
    if (tid == 9)  s_rs = g_rowsum[b];
    if (tid == 10) s_sw = g_sumw[b];
    __syncthreads();

    int v = blockIdx.x * 256 + tid;
    if (v >= Vv) return;
    const size_t BV = (size_t)Bq * Vv;
    const size_t off = (size_t)b * Vv + v;

    float blv = bl[off];
    float tp = 0.f;
    #pragma unroll
    for (int j = 0; j < Kk; ++j) if (ts[j] == v) tp += ws[j];

    float Z  = s_sw + (float)Vv * EPSV;
    float pk = (tp + EPSV) / Z;
    float pb = expf(blv - s_rm) / s_rs;
    float pi = (1.0f - LAM) * pb + LAM * pk;

    if ((long long)off < out_size)            out[off]          = logf(pi);
    if ((long long)(BV + off) < out_size)     out[BV + off]     = blv;
    if ((long long)(2 * BV + off) < out_size) out[2 * BV + off] = logf(tp + EPSV);
}

// =====================================================================
extern "C" void kernel_launch(void* const* d_in, const int* in_sizes, int n_in,
                              void* d_out, int out_size) {
    const float* qh   = (const float*)d_in[0];   // [B, D] f32
    const float* bl   = (const float*)d_in[1];   // [B, V] f32
    const float* keys = (const float*)d_in[2];   // [N, D] f32
    const void*  vals = d_in[3];                 // [N] int64 (or int32)
    float* out = (float*)d_out;

    k_scores<<<NCHUNK, 256>>>(qh, keys);
    k_topk<<<Bq, 512>>>(vals);
    k_rowstats<<<Bq, 256>>>(bl);
    dim3 g3((Vv + 255) / 256, Bq);
    k_final<<<g3, 256>>>(bl, out, (long long)out_size);
}

// round 3
// speedup vs baseline: 2.6417x; 2.6417x over previous
#include <cuda_runtime.h>
#include <math.h>
#include <stdint.h>

// ---------------- problem constants ----------------
#define Bq   64
#define Dd   768
#define Nn   262144
#define Vv   50257
#define Kk   8
#define TEMP 10.0f
#define LAM  0.25f
#define EPSV 1e-10f

#define KPC    256                 // keys per CTA
#define NCHUNK (Nn / KPC)          // 1024
#define KC     32                  // d-elements per pipeline stage
#define NKC    (Dd / KC)           // 24
#define TOPC   16                  // candidates rescored exactly

#define STRIDE 36                  // padded floats per smem row (conflict-free)

// dynamic SMEM layout (bytes)
#define SM_K2   0u                                   // 256 floats = 1024 B
#define SM_K    1024u                                // 2 stages x 256 x 36 x 4 = 73728
#define SM_Q    (SM_K + 2u * KPC * STRIDE * 4u)      // 74752; 2 stages x 64 x 36 x 4 = 18432
#define SM_T    1024u                                // sT: 64 x 260 floats (reuses K stages)
#define SMEM_BYTES (SM_Q + 2u * 64u * STRIDE * 4u)   // 93184

// ---------------- scratch ----------------
__device__ float g_cs[Bq * NCHUNK * Kk];
__device__ int   g_ci[Bq * NCHUNK * Kk];
__device__ float g_w[Bq * Kk];
__device__ int   g_tok[Bq * Kk];
__device__ float g_sumw[Bq];
__device__ float g_rowmax[Bq];
__device__ float g_rowsum[Bq];

// ---------------- helpers ----------------
__device__ __forceinline__ unsigned smem_u32(const void* p) {
    unsigned a;
    asm("{ .reg .u64 t; cvta.to.shared.u64 t, %1; cvt.u32.u64 %0, t; }" : "=r"(a) : "l"(p));
    return a;
}
__device__ __forceinline__ void cp16(unsigned dst, const void* src) {
    asm volatile("cp.async.cg.shared.global [%0], [%1], 16;" :: "r"(dst), "l"(src));
}
__device__ __forceinline__ void cp_commit() { asm volatile("cp.async.commit_group;" ::: "memory"); }
template<int N> __device__ __forceinline__ void cp_wait() { asm volatile("cp.async.wait_group %0;" :: "n"(N) : "memory"); }

// m16n8k8 tf32 mma (sm_80 ISA, works on compute_103)
__device__ __forceinline__ void mma_tf32(float c[4],
                                         unsigned a0, unsigned a1, unsigned a2, unsigned a3,
                                         unsigned b0, unsigned b1) {
    asm volatile(
        "mma.sync.aligned.m16n8k8.row.col.f32.tf32.tf32.f32 "
        "{%0,%1,%2,%3}, {%4,%5,%6,%7}, {%8,%9}, {%0,%1,%2,%3};"
        : "+f"(c[0]), "+f"(c[1]), "+f"(c[2]), "+f"(c[3])
        : "r"(a0), "r"(a1), "r"(a2), "r"(a3), "r"(b0), "r"(b1));
}

// =====================================================================
// Kernel 1: warp-MMA TF32  S[256 keys, 64 q] = K . Q^T, minus ||k||^2/2,
// then per-chunk per-query top-8 candidates.
// =====================================================================
__device__ __forceinline__ void load_stage(unsigned smb, int tid,
                                           const float* __restrict__ keys,
                                           const float* __restrict__ qh,
                                           int kBase, int kc, int s) {
    const float* kp = keys + (size_t)kBase * Dd + kc * KC;
    unsigned abase = smb + SM_K + s * (KPC * STRIDE * 4);
    #pragma unroll
    for (int i = 0; i < 8; ++i) {
        int g = tid + i * 256;
        int r = g >> 3, j = g & 7;
        cp16(abase + r * (STRIDE * 4) + j * 16, kp + (size_t)r * Dd + j * 4);
    }
    unsigned bbase = smb + SM_Q + s * (64 * STRIDE * 4);
    #pragma unroll
    for (int i = 0; i < 2; ++i) {
        int g = tid + i * 256;
        int r = g >> 3, j = g & 7;
        cp16(bbase + r * (STRIDE * 4) + j * 16, qh + (size_t)r * Dd + kc * KC + j * 4);
    }
    cp_commit();
}

__global__ void __launch_bounds__(256, 2)
k_scores_mma(const float* __restrict__ qh, const float* __restrict__ keys) {
    extern __shared__ char sm[];
    const unsigned smb = smem_u32(sm);
    const int tid = threadIdx.x;
    const int w   = tid >> 5;          // warp id: keys [w*32, w*32+32)
    const int lane = tid & 31;
    const int g = lane >> 2;           // groupID
    const int t = lane & 3;            // thread-in-group
    const int kBase = blockIdx.x * KPC;

    float c[2][8][4];
    #pragma unroll
    for (int m = 0; m < 2; ++m)
        #pragma unroll
        for (int n = 0; n < 8; ++n)
            #pragma unroll
            for (int v = 0; v < 4; ++v) c[m][n][v] = 0.f;
    float k2 = 0.f;

    load_stage(smb, tid, keys, qh, kBase, 0, 0);
    load_stage(smb, tid, keys, qh, kBase, 1, 1);

    for (int kc = 0; kc < NKC; ++kc) {
        const int s = kc & 1;
        if (kc < NKC - 1) cp_wait<1>(); else cp_wait<0>();
        __syncthreads();

        const float* ksm = (const float*)(sm + SM_K + s * (KPC * STRIDE * 4));
        const float* qsm = (const float*)(sm + SM_Q + s * (64 * STRIDE * 4));

        #pragma unroll
        for (int ks = 0; ks < 4; ++ks) {
            const int cb = ks * 8 + t;
            unsigned a[2][4];
            #pragma unroll
            for (int m = 0; m < 2; ++m) {
                const int r0 = w * 32 + m * 16 + g;
                a[m][0] = __float_as_uint(ksm[r0 * STRIDE + cb]);
                a[m][1] = __float_as_uint(ksm[(r0 + 8) * STRIDE + cb]);
                a[m][2] = __float_as_uint(ksm[r0 * STRIDE + cb + 4]);
                a[m][3] = __float_as_uint(ksm[(r0 + 8) * STRIDE + cb + 4]);
            }
            #pragma unroll
            for (int n = 0; n < 8; ++n) {
                const int qr = n * 8 + g;
                unsigned b0 = __float_as_uint(qsm[qr * STRIDE + cb]);
                unsigned b1 = __float_as_uint(qsm[qr * STRIDE + cb + 4]);
                mma_tf32(c[0][n], a[0][0], a[0][1], a[0][2], a[0][3], b0, b1);
                mma_tf32(c[1][n], a[1][0], a[1][1], a[1][2], a[1][3], b0, b1);
            }
        }

        // ||k||^2 partial: thread tid owns key row tid; rotated cols -> conflict-free
        {
            const int rot = (tid & 31) >> 3;
            #pragma unroll
            for (int i = 0; i < 32; ++i) {
                int cc = (i + rot) & 31;
                float v = ksm[tid * STRIDE + cc];
                k2 = fmaf(v, v, k2);
            }
        }
        __syncthreads();
        if (kc + 2 < NKC) load_stage(smb, tid, keys, qh, kBase, kc + 2, s);
    }

    ((float*)(sm + SM_K2))[tid] = 0.5f * k2;
    __syncthreads();

    // ---- write scores (minus 0.5||k||^2) to sT[query][key] ----
    float* sT = (float*)(sm + SM_T);
    const float* hk2 = (const float*)(sm + SM_K2);
    {
        float h[2][2];
        #pragma unroll
        for (int m = 0; m < 2; ++m) {
            h[m][0] = hk2[w * 32 + m * 16 + g];
            h[m][1] = hk2[w * 32 + m * 16 + g + 8];
        }
        #pragma unroll
        for (int m = 0; m < 2; ++m) {
            const int k0 = w * 32 + m * 16 + g;
            #pragma unroll
            for (int n = 0; n < 8; ++n) {
                const int q0 = n * 8 + 2 * t;
                sT[q0 * 260 + k0]           = c[m][n][0] - h[m][0];
                sT[(q0 + 1) * 260 + k0]     = c[m][n][1] - h[m][0];
                sT[q0 * 260 + k0 + 8]       = c[m][n][2] - h[m][1];
                sT[(q0 + 1) * 260 + k0 + 8] = c[m][n][3] - h[m][1];
            }
        }
    }
    __syncthreads();

    // ---- per-query top-8 over this chunk's 256 keys (4 threads/query) ----
    {
        const int q = tid >> 2, part = tid & 3;
        float lv[8]; int li[8];
        #pragma unroll
        for (int j = 0; j < 8; ++j) { lv[j] = -3.4e38f; li[j] = 0; }
        const float* row = sT + q * 260 + part * 64;
        #pragma unroll 4
        for (int i = 0; i < 16; ++i) {
            float4 v = *reinterpret_cast<const float4*>(row + i * 4);
            int bidx = kBase + part * 64 + i * 4;
            float vs[4] = {v.x, v.y, v.z, v.w};
            #pragma unroll
            for (int cc = 0; cc < 4; ++cc) {
                if (vs[cc] > lv[7]) {
                    lv[7] = vs[cc]; li[7] = bidx + cc;
                    #pragma unroll
                    for (int tt = 7; tt >= 1; --tt)
                        if (lv[tt] > lv[tt - 1]) {
                            float tv = lv[tt]; lv[tt] = lv[tt - 1]; lv[tt - 1] = tv;
                            int   ti = li[tt]; li[tt] = li[tt - 1]; li[tt - 1] = ti;
                        }
                }
            }
        }
        const int sl = lane & 3;
        for (int r = 0; r < Kk; ++r) {
            float mv = lv[0]; int mi = li[0]; int ml = sl;
            #pragma unroll
            for (int off = 1; off < 4; off <<= 1) {
                float ov = __shfl_xor_sync(0xffffffffu, mv, off);
                int   oi = __shfl_xor_sync(0xffffffffu, mi, off);
                int   ol = __shfl_xor_sync(0xffffffffu, ml, off);
                if (ov > mv) { mv = ov; mi = oi; ml = ol; }
            }
            if (ml == sl) {
                #pragma unroll
                for (int tt = 0; tt < 7; ++tt) { lv[tt] = lv[tt + 1]; li[tt] = li[tt + 1]; }
                lv[7] = -3.4e38f;
            }
            if (sl == 0) {
                size_t o = ((size_t)q * NCHUNK + blockIdx.x) * Kk + r;
                g_cs[o] = mv; g_ci[o] = mi;
            }
        }
    }
}

// =====================================================================
// Kernel 2: global approx top-16 per query -> exact fp32 rescore -> top-8
// =====================================================================
__global__ __launch_bounds__(256)
void k_topk(const float* __restrict__ qh, const float* __restrict__ keys,
            const void* __restrict__ values_raw) {
    __shared__ float sval[256 * 16];
    __shared__ int   sidx[256 * 16];
    __shared__ float rv[256];
    __shared__ int   rp[256];
    __shared__ float topv[TOPC];
    __shared__ int   topi[TOPC];
    __shared__ float exacts[TOPC];
    __shared__ int   is64;

    const int b = blockIdx.x, tid = threadIdx.x;

    if (tid == 0) is64 = 1;
    __syncthreads();
    {
        const int2* vv = (const int2*)values_raw;
        int bad = 0;
        #pragma unroll
        for (int s = 0; s < 16; ++s) bad |= vv[tid + s * 256].y;
        if (bad != 0) is64 = 0;
    }

    float lv[16]; int li[16];
    #pragma unroll
    for (int j = 0; j < 16; ++j) { lv[j] = -3.4e38f; li[j] = 0; }
    const size_t base = (size_t)b * (NCHUNK * Kk);
    for (int s = 0; s < 32; ++s) {
        int j = tid + s * 256;
        float v = g_cs[base + j];
        int  ix = g_ci[base + j];
        if (v > lv[15]) {
            lv[15] = v; li[15] = ix;
            #pragma unroll
            for (int tt = 15; tt >= 1; --tt)
                if (lv[tt] > lv[tt - 1]) {
                    float tv = lv[tt]; lv[tt] = lv[tt - 1]; lv[tt - 1] = tv;
                    int   ti = li[tt]; li[tt] = li[tt - 1]; li[tt - 1] = ti;
                }
        }
    }
    #pragma unroll
    for (int j = 0; j < 16; ++j) { sval[tid * 16 + j] = lv[j]; sidx[tid * 16 + j] = li[j]; }
    __syncthreads();

    for (int r = 0; r < TOPC; ++r) {
        float best = -3.4e38f; int bp = 0;
        #pragma unroll
        for (int s = 0; s < 16; ++s) {
            int p = tid * 16 + s;
            if (sval[p] > best) { best = sval[p]; bp = p; }
        }
        rv[tid] = best; rp[tid] = bp;
        __syncthreads();
        for (int st = 128; st > 0; st >>= 1) {
            if (tid < st && rv[tid + st] > rv[tid]) { rv[tid] = rv[tid + st]; rp[tid] = rp[tid + st]; }
            __syncthreads();
        }
        if (tid == 0) { topv[r] = rv[0]; topi[r] = sidx[rp[0]]; sval[rp[0]] = -3.4e38f; }
        __syncthreads();
    }

    // exact fp32 rescore: 16 threads per candidate
    {
        int j = tid >> 4, l = tid & 15;
        const float* kr = keys + (size_t)topi[j] * Dd;
        const float* qr = qh + (size_t)b * Dd;
        float dot = 0.f, kk = 0.f;
        for (int d = l; d < Dd; d += 16) {
            float kv = kr[d];
            dot = fmaf(qr[d], kv, dot);
            kk  = fmaf(kv, kv, kk);
        }
        #pragma unroll
        for (int off = 8; off > 0; off >>= 1) {
            dot += __shfl_xor_sync(0xffffffffu, dot, off);
            kk  += __shfl_xor_sync(0xffffffffu, kk, off);
        }
        if (l == 0) exacts[j] = dot - 0.5f * kk;
    }
    __syncthreads();

    if (tid == 0) {
        int order[Kk]; unsigned used = 0;
        for (int r = 0; r < Kk; ++r) {
            float best = -3.4e38f; int bj = 0;
            for (int j = 0; j < TOPC; ++j)
                if (!((used >> j) & 1u) && exacts[j] > best) { best = exacts[j]; bj = j; }
            used |= 1u << bj; order[r] = bj;
        }
        float m = exacts[order[0]];
        float e[Kk], se = 0.f;
        for (int r = 0; r < Kk; ++r) { e[r] = expf(2.f * (exacts[order[r]] - m) / TEMP); se += e[r]; }
        float sw = 0.f;
        for (int r = 0; r < Kk; ++r) {
            float wv = e[r] / se;
            g_w[b * Kk + r] = wv; sw += wv;
            int gi = topi[order[r]];
            int tok = is64 ? (int)((const long long*)values_raw)[gi]
                           : ((const int*)values_raw)[gi];
            g_tok[b * Kk + r] = tok;
        }
        g_sumw[b] = sw;
    }
}

// =====================================================================
// Kernel 3a: per-row max & sum(exp) of base_logits
// =====================================================================
__global__ __launch_bounds__(256)
void k_rowstats(const float* __restrict__ bl) {
    __shared__ float red[256];
    __shared__ float s_rm;
    const int b = blockIdx.x, tid = threadIdx.x;
    const float* row = bl + (size_t)b * Vv;

    float m = -3.4e38f;
    for (int v = tid; v < Vv; v += 256) m = fmaxf(m, row[v]);
    red[tid] = m; __syncthreads();
    for (int st = 128; st > 0; st >>= 1) {
        if (tid < st) red[tid] = fmaxf(red[tid], red[tid + st]);
        __syncthreads();
    }
    if (tid == 0) { s_rm = red[0]; g_rowmax[b] = red[0]; }
    __syncthreads();
    float rm = s_rm;

    float s = 0.f;
    for (int v = tid; v < Vv; v += 256) s += expf(row[v] - rm);
    red[tid] = s; __syncthreads();
    for (int st = 128; st > 0; st >>= 1) {
        if (tid < st) red[tid] += red[tid + st];
        __syncthreads();
    }
    if (tid == 0) g_rowsum[b] = red[0];
}

// =====================================================================
// Kernel 3b: final elementwise mix; writes (interpolated, base, knn)
// =====================================================================
__global__ __launch_bounds__(256)
void k_final(const float* __restrict__ bl, float* __restrict__ out, long long out_size) {
    __shared__ float ws[Kk]; __shared__ int ts[Kk];
    __shared__ float s_rm, s_rs, s_sw;
    const int b = blockIdx.y, tid = threadIdx.x;
    if (tid < Kk) { ws[tid] = g_w[b * Kk + tid]; ts[tid] = g_tok[b * Kk + tid]; }
    if (tid == 8)  s_rm = g_rowmax[b];
    if (tid == 9)  s_rs = g_rowsum[b];
    if (tid == 10) s_sw = g_sumw[b];
    __syncthreads();

    int v = blockIdx.x * 256 + tid;
    if (v >= Vv) return;
    const size_t BV = (size_t)Bq * Vv;
    const size_t off = (size_t)b * Vv + v;

    float blv = bl[off];
    float tp = 0.f;
    #pragma unroll
    for (int j = 0; j < Kk; ++j) if (ts[j] == v) tp += ws[j];

    float Z  = s_sw + (float)Vv * EPSV;
    float pk = (tp + EPSV) / Z;
    float pb = expf(blv - s_rm) / s_rs;
    float pi = (1.0f - LAM) * pb + LAM * pk;

    if ((long long)off < out_size)            out[off]          = logf(pi);
    if ((long long)(BV + off) < out_size)     out[BV + off]     = blv;
    if ((long long)(2 * BV + off) < out_size) out[2 * BV + off] = logf(tp + EPSV);
}

// =====================================================================
extern "C" void kernel_launch(void* const* d_in, const int* in_sizes, int n_in,
                              void* d_out, int out_size) {
    const float* qh   = (const float*)d_in[0];   // [B, D] f32
    const float* bl   = (const float*)d_in[1];   // [B, V] f32
    const float* keys = (const float*)d_in[2];   // [N, D] f32
    const void*  vals = d_in[3];                 // [N] int64 (or int32)
    float* out = (float*)d_out;

    cudaFuncSetAttribute(k_scores_mma, cudaFuncAttributeMaxDynamicSharedMemorySize, SMEM_BYTES);

    k_scores_mma<<<NCHUNK, 256, SMEM_BYTES>>>(qh, keys);
    k_topk<<<Bq, 256>>>(qh, keys, vals);
    k_rowstats<<<Bq, 256>>>(bl);
    dim3 g3((Vv + 255) / 256, Bq);
    k_final<<<g3, 256>>>(bl, out, (long long)out_size);
}